// round 2
// baseline (speedup 1.0000x reference)
#include <cuda_runtime.h>
#include <math.h>

#define NF 101
#define UNITS 125
#define G3 375
#define OUT 202
#define KSZ (UNITS*OUT)
#define NW (KSZ+OUT)
#define TT 70
#define STEPS1 56
#define GAMMA 28
#define BATCH 4096
#define CCONST 0.54132485f

// padded layouts
#define GU 128          // padded units
#define WROW 384        // 3 gates * 128
#define OPAD 256        // padded dense output row

#define OFF_WP 0
#define SZ_WP (NF*WROW)
#define OFF_UP (OFF_WP+SZ_WP)
#define SZ_UP (UNITS*WROW)
#define OFF_B0 (OFF_UP+SZ_UP)
#define OFF_B1 (OFF_B0+WROW)
#define OFF_KP (OFF_B1+WROW)
#define SZ_KP (GAMMA*UNITS*OPAD)
#define OFF_BIAS (OFF_KP+SZ_KP)
#define SZ_BIAS (GAMMA*OPAD)
#define SCRATCH_TOTAL (OFF_BIAS+SZ_BIAS)

__device__ __align__(16) float g_scratch[SCRATCH_TOTAL];

typedef unsigned long long u64;

// ---- packed f32x2 helpers (sm_103a) ----
__device__ __forceinline__ void fma2(u64& d, u64 a, u64 b){
    asm("fma.rn.f32x2 %0, %1, %2, %0;" : "+l"(d) : "l"(a), "l"(b));
}
__device__ __forceinline__ u64 pack2(float x, float y){
    u64 r; asm("mov.b64 %0, {%1,%2};" : "=l"(r) : "f"(x), "f"(y)); return r;
}
__device__ __forceinline__ float2 unpack2(u64 v){
    float2 r; asm("mov.b64 {%0,%1}, %2;" : "=f"(r.x), "=f"(r.y) : "l"(v)); return r;
}

// ---- math ----
__device__ __forceinline__ float sp(float x){          // softplus, stable
    float r = log1pf(__expf(x));
    return (x > 15.f) ? x : r;
}
__device__ __forceinline__ float sigm(float x){
    return __fdividef(1.f, 1.f + __expf(-x));
}
__device__ __forceinline__ float mytanh(float x){
    return __fdividef(2.f, 1.f + __expf(-2.f*x)) - 1.f;
}

// ---- weight prep helpers ----
__device__ __forceinline__ float dvw(int s, int w,
    const float* dv_loc, const float* dv_rho, const float* eps_w0, const float* eps_w)
{
    float sd = 1e-5f + 0.01f * sp(CCONST + dv_rho[w]);
    float e  = (s == 0) ? eps_w0[w] : eps_w[(size_t)(s-1)*NW + w];
    return dv_loc[w] + sd * e;
}

__global__ void prep_kernel(const float* __restrict__ W_k, const float* __restrict__ U,
                            const float* __restrict__ b,   const float* __restrict__ dv_loc,
                            const float* __restrict__ dv_rho, const float* __restrict__ eps_w0,
                            const float* __restrict__ eps_w)
{
    for (int i = blockIdx.x*blockDim.x + threadIdx.x; i < SCRATCH_TOTAL; i += gridDim.x*blockDim.x){
        float v = 0.f;
        if (i < OFF_UP){
            int idx = i - OFF_WP; int k = idx / WROW, c = idx % WROW;
            int g = c / GU, u = c % GU;
            v = (u < UNITS) ? W_k[k*G3 + g*UNITS + u] : 0.f;
        } else if (i < OFF_B0){
            int idx = i - OFF_UP; int k = idx / WROW, c = idx % WROW;
            int g = c / GU, u = c % GU;
            v = (u < UNITS) ? U[k*G3 + g*UNITS + u] : 0.f;
        } else if (i < OFF_B1){
            int c = i - OFF_B0; int g = c / GU, u = c % GU;
            v = (u < UNITS) ? b[g*UNITS + u] : 0.f;
        } else if (i < OFF_KP){
            int c = i - OFF_B1; int g = c / GU, u = c % GU;
            v = (u < UNITS) ? b[G3 + g*UNITS + u] : 0.f;
        } else if (i < OFF_BIAS){
            int idx = i - OFF_KP; int s = idx / (UNITS*OPAD);
            int rem = idx % (UNITS*OPAD); int u = rem / OPAD, o = rem % OPAD;
            if (o < OUT) v = dvw(s, u*OUT + o, dv_loc, dv_rho, eps_w0, eps_w);
        } else {
            int idx = i - OFF_BIAS; int s = idx / OPAD, o = idx % OPAD;
            if (o < OUT) v = dvw(s, KSZ + o, dv_loc, dv_rho, eps_w0, eps_w);
        }
        g_scratch[i] = v;
    }
}

// ---- main persistent RNN kernel ----
#define ROWS_W 4
#define WARPS 8
#define ROWS_CTA (ROWS_W*WARPS)      // 32
#define XSTRIDE 104                  // padded x row (in u64)
#define YSTRIDE 208

#define SMEM_BYTES (ROWS_CTA*GU*8 + ROWS_CTA*XSTRIDE*8 + ROWS_CTA*YSTRIDE*4)

__device__ __forceinline__ void gru_step(u64* hh, u64* xx, int lane)
{
    u64 amx[ROWS_W][3][2], ami[ROWS_W][3][2];
    const u64* b0 = (const u64*)(g_scratch + OFF_B0);
    const u64* b1 = (const u64*)(g_scratch + OFF_B1);
    #pragma unroll
    for (int g = 0; g < 3; ++g)
        #pragma unroll
        for (int j = 0; j < 2; ++j){
            u64 v0 = b0[g*64 + 2*lane + j];
            u64 v1 = b1[g*64 + 2*lane + j];
            #pragma unroll
            for (int r = 0; r < ROWS_W; ++r){ amx[r][g][j] = v0; ami[r][g][j] = v1; }
        }

    // mx = x @ W_k  (+b0)
    const float* Wp = g_scratch + OFF_WP + 4*lane;
    #pragma unroll 2
    for (int k = 0; k < NF; ++k){
        u64 xv[ROWS_W];
        #pragma unroll
        for (int r = 0; r < ROWS_W; ++r) xv[r] = xx[r*XSTRIDE + k];
        const float* wk = Wp + k*WROW;
        #pragma unroll
        for (int g = 0; g < 3; ++g){
            ulonglong2 w = *(const ulonglong2*)(wk + g*GU);
            #pragma unroll
            for (int r = 0; r < ROWS_W; ++r){
                fma2(amx[r][g][0], w.x, xv[r]);
                fma2(amx[r][g][1], w.y, xv[r]);
            }
        }
    }
    // mi = h @ U  (+b1)
    const float* Uq = g_scratch + OFF_UP + 4*lane;
    #pragma unroll 2
    for (int k = 0; k < UNITS; ++k){
        u64 hv[ROWS_W];
        #pragma unroll
        for (int r = 0; r < ROWS_W; ++r) hv[r] = hh[r*GU + k];
        const float* wk = Uq + k*WROW;
        #pragma unroll
        for (int g = 0; g < 3; ++g){
            ulonglong2 w = *(const ulonglong2*)(wk + g*GU);
            #pragma unroll
            for (int r = 0; r < ROWS_W; ++r){
                fma2(ami[r][g][0], w.x, hv[r]);
                fma2(ami[r][g][1], w.y, hv[r]);
            }
        }
    }
    __syncwarp();   // all lanes done reading old h
    #pragma unroll
    for (int r = 0; r < ROWS_W; ++r){
        #pragma unroll
        for (int j = 0; j < 2; ++j){
            float2 xz = unpack2(amx[r][0][j]), rz = unpack2(ami[r][0][j]);
            float2 xr = unpack2(amx[r][1][j]), rr = unpack2(ami[r][1][j]);
            float2 xh = unpack2(amx[r][2][j]), rh = unpack2(ami[r][2][j]);
            int u = 4*lane + 2*j;
            float hold0 = unpack2(hh[r*GU + u]).x;
            float hold1 = unpack2(hh[r*GU + u + 1]).x;
            float z0 = sigm(xz.x + rz.x), z1 = sigm(xz.y + rz.y);
            float g0 = sigm(xr.x + rr.x), g1 = sigm(xr.y + rr.y);
            float c0 = mytanh(xh.x + g0*rh.x), c1 = mytanh(xh.y + g1*rh.y);
            float h0 = z0*hold0 + (1.f - z0)*c0;
            float h1 = z1*hold1 + (1.f - z1)*c1;
            hh[r*GU + u]     = pack2(h0, h0);
            hh[r*GU + u + 1] = pack2(h1, h1);
        }
    }
    __syncwarp();
}

__device__ __forceinline__ void dense_step(int s, u64* hh, float* yy, int lane)
{
    u64 acc[ROWS_W][2][2];
    const u64* bias = (const u64*)(g_scratch + OFF_BIAS + s*OPAD);
    #pragma unroll
    for (int oc = 0; oc < 2; ++oc)
        #pragma unroll
        for (int j = 0; j < 2; ++j){
            u64 v = bias[oc*64 + 2*lane + j];
            #pragma unroll
            for (int r = 0; r < ROWS_W; ++r) acc[r][oc][j] = v;
        }
    const float* Kp = g_scratch + OFF_KP + (size_t)s*UNITS*OPAD + 4*lane;
    #pragma unroll 2
    for (int u = 0; u < UNITS; ++u){
        const float* kr = Kp + u*OPAD;
        ulonglong2 w0 = *(const ulonglong2*)(kr);
        ulonglong2 w1 = *(const ulonglong2*)(kr + GU);
        #pragma unroll
        for (int r = 0; r < ROWS_W; ++r){
            u64 hv = hh[r*GU + u];
            fma2(acc[r][0][0], w0.x, hv); fma2(acc[r][0][1], w0.y, hv);
            fma2(acc[r][1][0], w1.x, hv); fma2(acc[r][1][1], w1.y, hv);
        }
    }
    #pragma unroll
    for (int r = 0; r < ROWS_W; ++r)
        #pragma unroll
        for (int oc = 0; oc < 2; ++oc)
            #pragma unroll
            for (int j = 0; j < 2; ++j){
                int o = oc*GU + 4*lane + 2*j;
                if (o < YSTRIDE){
                    float2 v = unpack2(acc[r][oc][j]);
                    yy[r*YSTRIDE + o]     = v.x;
                    yy[r*YSTRIDE + o + 1] = v.y;
                }
            }
    __syncwarp();
}

__global__ void __launch_bounds__(256, 1)
rnn_kernel(const float* __restrict__ inputs, const float* __restrict__ eps_s,
           float* __restrict__ out)
{
    extern __shared__ unsigned char smem[];
    u64*   sh_h = (u64*)smem;                                          // 32*128 u64
    u64*   sh_x = (u64*)(smem + ROWS_CTA*GU*8);                        // 32*104 u64
    float* sh_y = (float*)(smem + ROWS_CTA*GU*8 + ROWS_CTA*XSTRIDE*8); // 32*208 f32

    const int lane = threadIdx.x & 31;
    const int warp = threadIdx.x >> 5;
    const int r0l  = warp * ROWS_W;
    const int r0g  = blockIdx.x * ROWS_CTA + r0l;

    u64*   hh = sh_h + r0l*GU;
    u64*   xx = sh_x + r0l*XSTRIDE;
    float* yy = sh_y + r0l*YSTRIDE;

    // h = 0
    #pragma unroll
    for (int r = 0; r < ROWS_W; ++r)
        #pragma unroll
        for (int e = 0; e < 4; ++e) hh[r*GU + 4*lane + e] = 0ULL;
    __syncwarp();

    // phase 1: teacher-forced GRU over 56 steps
    for (int t = 0; t < STEPS1; ++t){
        #pragma unroll
        for (int r = 0; r < ROWS_W; ++r){
            const float* xp = inputs + ((size_t)(r0g + r)*TT + t)*NF;
            for (int k = lane; k < NF; k += 32){
                float v = xp[k];
                xx[r*XSTRIDE + k] = pack2(v, v);
            }
        }
        __syncwarp();
        gru_step(hh, xx, lane);
    }

    // y0 + feedback loop
    for (int s = 0; s < GAMMA; ++s){
        if (s > 0){
            #pragma unroll
            for (int r = 0; r < ROWS_W; ++r){
                const float* ep = eps_s + ((size_t)(s-1)*BATCH + (r0g + r))*NF;
                for (int k = lane; k < NF; k += 32){
                    float loc = yy[r*YSTRIDE + k];
                    float sc  = 1e-5f + 0.05f*sp(CCONST + yy[r*YSTRIDE + NF + k]);
                    float xv  = loc + sc*ep[k];
                    xx[r*XSTRIDE + k] = pack2(xv, xv);
                }
            }
            __syncwarp();
            gru_step(hh, xx, lane);
        }
        dense_step(s, hh, yy, lane);
        // emit outputs: loc passthrough, scale transform
        #pragma unroll
        for (int r = 0; r < ROWS_W; ++r){
            float* op = out + ((size_t)(r0g + r)*GAMMA + s)*OUT;
            for (int o = lane; o < OUT; o += 32){
                float v = yy[r*YSTRIDE + o];
                if (o >= NF) v = 1e-5f + 0.05f*sp(CCONST + v);
                op[o] = v;
            }
        }
        __syncwarp();
    }
}

extern "C" void kernel_launch(void* const* d_in, const int* in_sizes, int n_in,
                              void* d_out, int out_size)
{
    const float* inputs = (const float*)d_in[0];
    const float* W_k    = (const float*)d_in[1];
    const float* U      = (const float*)d_in[2];
    const float* b      = (const float*)d_in[3];
    const float* dv_loc = (const float*)d_in[4];
    const float* dv_rho = (const float*)d_in[5];
    const float* eps_w0 = (const float*)d_in[6];
    const float* eps_w  = (const float*)d_in[7];
    const float* eps_s  = (const float*)d_in[8];
    float* out = (float*)d_out;

    (void)in_sizes; (void)n_in; (void)out_size;

    cudaFuncSetAttribute(rnn_kernel, cudaFuncAttributeMaxDynamicSharedMemorySize, SMEM_BYTES);

    prep_kernel<<<1024, 256>>>(W_k, U, b, dv_loc, dv_rho, eps_w0, eps_w);
    rnn_kernel<<<BATCH/ROWS_CTA, 256, SMEM_BYTES>>>(inputs, eps_s, out);
}

// round 3
// speedup vs baseline: 1.3904x; 1.3904x over previous
#include <cuda_runtime.h>
#include <math.h>

#define NF 101
#define UNITS 125
#define G3 375
#define OUT 202
#define KSZ (UNITS*OUT)
#define NW (KSZ+OUT)
#define TT 70
#define STEPS1 56
#define GAMMA 28
#define BATCH 4096
#define CCONST 0.54132485f

// padded layouts
#define GU 128          // padded units
#define WROW 384        // 3 gates * 128
#define OPAD 256        // padded dense output row

#define OFF_WP 0
#define SZ_WP (NF*WROW)
#define OFF_UP (OFF_WP+SZ_WP)
#define SZ_UP (UNITS*WROW)
#define OFF_B0 (OFF_UP+SZ_UP)
#define OFF_B1 (OFF_B0+WROW)
#define OFF_KP (OFF_B1+WROW)
#define SZ_KP (GAMMA*UNITS*OPAD)
#define OFF_BIAS (OFF_KP+SZ_KP)
#define SZ_BIAS (GAMMA*OPAD)
#define SCRATCH_TOTAL (OFF_BIAS+SZ_BIAS)

__device__ __align__(16) float g_scratch[SCRATCH_TOTAL];

typedef unsigned long long u64;

// ---- packed f32x2 helpers (sm_103a) ----
__device__ __forceinline__ void fma2(u64& d, u64 a, u64 b){
    asm("fma.rn.f32x2 %0, %1, %2, %0;" : "+l"(d) : "l"(a), "l"(b));
}
__device__ __forceinline__ u64 pack2(float x, float y){
    u64 r; asm("mov.b64 %0, {%1,%2};" : "=l"(r) : "f"(x), "f"(y)); return r;
}
__device__ __forceinline__ float2 unpack2(u64 v){
    float2 r; asm("mov.b64 {%0,%1}, %2;" : "=f"(r.x), "=f"(r.y) : "l"(v)); return r;
}

// ---- math ----
__device__ __forceinline__ float sp(float x){          // softplus, stable
    float r = log1pf(__expf(x));
    return (x > 15.f) ? x : r;
}
__device__ __forceinline__ float sigm(float x){
    return __fdividef(1.f, 1.f + __expf(-x));
}
__device__ __forceinline__ float mytanh(float x){
    return __fdividef(2.f, 1.f + __expf(-2.f*x)) - 1.f;
}

// ---- weight prep helpers ----
__device__ __forceinline__ float dvw(int s, int w,
    const float* dv_loc, const float* dv_rho, const float* eps_w0, const float* eps_w)
{
    float sd = 1e-5f + 0.01f * sp(CCONST + dv_rho[w]);
    float e  = (s == 0) ? eps_w0[w] : eps_w[(size_t)(s-1)*NW + w];
    return dv_loc[w] + sd * e;
}

__global__ void prep_kernel(const float* __restrict__ W_k, const float* __restrict__ U,
                            const float* __restrict__ b,   const float* __restrict__ dv_loc,
                            const float* __restrict__ dv_rho, const float* __restrict__ eps_w0,
                            const float* __restrict__ eps_w)
{
    for (int i = blockIdx.x*blockDim.x + threadIdx.x; i < SCRATCH_TOTAL; i += gridDim.x*blockDim.x){
        float v = 0.f;
        if (i < OFF_UP){
            int idx = i - OFF_WP; int k = idx / WROW, c = idx % WROW;
            int g = c / GU, u = c % GU;
            v = (u < UNITS) ? W_k[k*G3 + g*UNITS + u] : 0.f;
        } else if (i < OFF_B0){
            int idx = i - OFF_UP; int k = idx / WROW, c = idx % WROW;
            int g = c / GU, u = c % GU;
            v = (u < UNITS) ? U[k*G3 + g*UNITS + u] : 0.f;
        } else if (i < OFF_B1){
            int c = i - OFF_B0; int g = c / GU, u = c % GU;
            v = (u < UNITS) ? b[g*UNITS + u] : 0.f;
        } else if (i < OFF_KP){
            int c = i - OFF_B1; int g = c / GU, u = c % GU;
            v = (u < UNITS) ? b[G3 + g*UNITS + u] : 0.f;
        } else if (i < OFF_BIAS){
            int idx = i - OFF_KP; int s = idx / (UNITS*OPAD);
            int rem = idx % (UNITS*OPAD); int u = rem / OPAD, o = rem % OPAD;
            if (o < OUT) v = dvw(s, u*OUT + o, dv_loc, dv_rho, eps_w0, eps_w);
        } else {
            int idx = i - OFF_BIAS; int s = idx / OPAD, o = idx % OPAD;
            if (o < OUT) v = dvw(s, KSZ + o, dv_loc, dv_rho, eps_w0, eps_w);
        }
        g_scratch[i] = v;
    }
}

// ---- main persistent RNN kernel ----
#define ROWS_W 2
#define WARPS 8
#define ROWS_CTA (ROWS_W*WARPS)      // 16
#define XSTRIDE 104                  // padded x row (in u64)
#define YSTRIDE 208

#define SMEM_BYTES (ROWS_CTA*GU*8 + ROWS_CTA*XSTRIDE*8 + ROWS_CTA*YSTRIDE*4)

__device__ __forceinline__ void gru_step(u64* hh, u64* xx, int lane)
{
    u64 amx[ROWS_W][3][2], ami[ROWS_W][3][2];
    const u64* b0 = (const u64*)(g_scratch + OFF_B0);
    const u64* b1 = (const u64*)(g_scratch + OFF_B1);
    #pragma unroll
    for (int g = 0; g < 3; ++g)
        #pragma unroll
        for (int j = 0; j < 2; ++j){
            u64 v0 = b0[g*64 + 2*lane + j];
            u64 v1 = b1[g*64 + 2*lane + j];
            #pragma unroll
            for (int r = 0; r < ROWS_W; ++r){ amx[r][g][j] = v0; ami[r][g][j] = v1; }
        }

    // mx = x @ W_k  (+b0)
    const float* Wp = g_scratch + OFF_WP + 4*lane;
    #pragma unroll 4
    for (int k = 0; k < NF; ++k){
        u64 xv[ROWS_W];
        #pragma unroll
        for (int r = 0; r < ROWS_W; ++r) xv[r] = xx[r*XSTRIDE + k];
        const float* wk = Wp + k*WROW;
        #pragma unroll
        for (int g = 0; g < 3; ++g){
            ulonglong2 w = *(const ulonglong2*)(wk + g*GU);
            #pragma unroll
            for (int r = 0; r < ROWS_W; ++r){
                fma2(amx[r][g][0], w.x, xv[r]);
                fma2(amx[r][g][1], w.y, xv[r]);
            }
        }
    }
    // mi = h @ U  (+b1)
    const float* Uq = g_scratch + OFF_UP + 4*lane;
    #pragma unroll 4
    for (int k = 0; k < UNITS; ++k){
        u64 hv[ROWS_W];
        #pragma unroll
        for (int r = 0; r < ROWS_W; ++r) hv[r] = hh[r*GU + k];
        const float* wk = Uq + k*WROW;
        #pragma unroll
        for (int g = 0; g < 3; ++g){
            ulonglong2 w = *(const ulonglong2*)(wk + g*GU);
            #pragma unroll
            for (int r = 0; r < ROWS_W; ++r){
                fma2(ami[r][g][0], w.x, hv[r]);
                fma2(ami[r][g][1], w.y, hv[r]);
            }
        }
    }
    __syncwarp();   // all lanes done reading old h
    #pragma unroll
    for (int r = 0; r < ROWS_W; ++r){
        #pragma unroll
        for (int j = 0; j < 2; ++j){
            float2 xz = unpack2(amx[r][0][j]), rz = unpack2(ami[r][0][j]);
            float2 xr = unpack2(amx[r][1][j]), rr = unpack2(ami[r][1][j]);
            float2 xh = unpack2(amx[r][2][j]), rh = unpack2(ami[r][2][j]);
            int u = 4*lane + 2*j;
            float hold0 = unpack2(hh[r*GU + u]).x;
            float hold1 = unpack2(hh[r*GU + u + 1]).x;
            float z0 = sigm(xz.x + rz.x), z1 = sigm(xz.y + rz.y);
            float g0 = sigm(xr.x + rr.x), g1 = sigm(xr.y + rr.y);
            float c0 = mytanh(xh.x + g0*rh.x), c1 = mytanh(xh.y + g1*rh.y);
            float h0 = z0*hold0 + (1.f - z0)*c0;
            float h1 = z1*hold1 + (1.f - z1)*c1;
            hh[r*GU + u]     = pack2(h0, h0);
            hh[r*GU + u + 1] = pack2(h1, h1);
        }
    }
    __syncwarp();
}

__device__ __forceinline__ void dense_step(int s, u64* hh, float* yy, int lane)
{
    u64 acc[ROWS_W][2][2];
    const u64* bias = (const u64*)(g_scratch + OFF_BIAS + s*OPAD);
    #pragma unroll
    for (int oc = 0; oc < 2; ++oc)
        #pragma unroll
        for (int j = 0; j < 2; ++j){
            u64 v = bias[oc*64 + 2*lane + j];
            #pragma unroll
            for (int r = 0; r < ROWS_W; ++r) acc[r][oc][j] = v;
        }
    const float* Kp = g_scratch + OFF_KP + (size_t)s*UNITS*OPAD + 4*lane;
    #pragma unroll 4
    for (int u = 0; u < UNITS; ++u){
        const float* kr = Kp + u*OPAD;
        ulonglong2 w0 = *(const ulonglong2*)(kr);
        ulonglong2 w1 = *(const ulonglong2*)(kr + GU);
        #pragma unroll
        for (int r = 0; r < ROWS_W; ++r){
            u64 hv = hh[r*GU + u];
            fma2(acc[r][0][0], w0.x, hv); fma2(acc[r][0][1], w0.y, hv);
            fma2(acc[r][1][0], w1.x, hv); fma2(acc[r][1][1], w1.y, hv);
        }
    }
    #pragma unroll
    for (int r = 0; r < ROWS_W; ++r)
        #pragma unroll
        for (int oc = 0; oc < 2; ++oc)
            #pragma unroll
            for (int j = 0; j < 2; ++j){
                int o = oc*GU + 4*lane + 2*j;
                if (o < YSTRIDE){
                    float2 v = unpack2(acc[r][oc][j]);
                    yy[r*YSTRIDE + o]     = v.x;
                    yy[r*YSTRIDE + o + 1] = v.y;
                }
            }
    __syncwarp();
}

__global__ void __launch_bounds__(256, 2)
rnn_kernel(const float* __restrict__ inputs, const float* __restrict__ eps_s,
           float* __restrict__ out)
{
    extern __shared__ unsigned char smem[];
    u64*   sh_h = (u64*)smem;                                          // 16*128 u64
    u64*   sh_x = (u64*)(smem + ROWS_CTA*GU*8);                        // 16*104 u64
    float* sh_y = (float*)(smem + ROWS_CTA*GU*8 + ROWS_CTA*XSTRIDE*8); // 16*208 f32

    const int lane = threadIdx.x & 31;
    const int warp = threadIdx.x >> 5;
    const int r0l  = warp * ROWS_W;
    const int r0g  = blockIdx.x * ROWS_CTA + r0l;

    u64*   hh = sh_h + r0l*GU;
    u64*   xx = sh_x + r0l*XSTRIDE;
    float* yy = sh_y + r0l*YSTRIDE;

    // h = 0
    #pragma unroll
    for (int r = 0; r < ROWS_W; ++r)
        #pragma unroll
        for (int e = 0; e < 4; ++e) hh[r*GU + 4*lane + e] = 0ULL;
    __syncwarp();

    // phase 1: teacher-forced GRU over 56 steps
    for (int t = 0; t < STEPS1; ++t){
        #pragma unroll
        for (int r = 0; r < ROWS_W; ++r){
            const float* xp = inputs + ((size_t)(r0g + r)*TT + t)*NF;
            for (int k = lane; k < NF; k += 32){
                float v = xp[k];
                xx[r*XSTRIDE + k] = pack2(v, v);
            }
        }
        __syncwarp();
        gru_step(hh, xx, lane);
    }

    // y0 + feedback loop
    for (int s = 0; s < GAMMA; ++s){
        if (s > 0){
            #pragma unroll
            for (int r = 0; r < ROWS_W; ++r){
                const float* ep = eps_s + ((size_t)(s-1)*BATCH + (r0g + r))*NF;
                for (int k = lane; k < NF; k += 32){
                    float loc = yy[r*YSTRIDE + k];
                    float sc  = 1e-5f + 0.05f*sp(CCONST + yy[r*YSTRIDE + NF + k]);
                    float xv  = loc + sc*ep[k];
                    xx[r*XSTRIDE + k] = pack2(xv, xv);
                }
            }
            __syncwarp();
            gru_step(hh, xx, lane);
        }
        dense_step(s, hh, yy, lane);
        // emit outputs: loc passthrough, scale transform
        #pragma unroll
        for (int r = 0; r < ROWS_W; ++r){
            float* op = out + ((size_t)(r0g + r)*GAMMA + s)*OUT;
            for (int o = lane; o < OUT; o += 32){
                float v = yy[r*YSTRIDE + o];
                if (o >= NF) v = 1e-5f + 0.05f*sp(CCONST + v);
                op[o] = v;
            }
        }
        __syncwarp();
    }
}

extern "C" void kernel_launch(void* const* d_in, const int* in_sizes, int n_in,
                              void* d_out, int out_size)
{
    const float* inputs = (const float*)d_in[0];
    const float* W_k    = (const float*)d_in[1];
    const float* U      = (const float*)d_in[2];
    const float* b      = (const float*)d_in[3];
    const float* dv_loc = (const float*)d_in[4];
    const float* dv_rho = (const float*)d_in[5];
    const float* eps_w0 = (const float*)d_in[6];
    const float* eps_w  = (const float*)d_in[7];
    const float* eps_s  = (const float*)d_in[8];
    float* out = (float*)d_out;

    (void)in_sizes; (void)n_in; (void)out_size;

    cudaFuncSetAttribute(rnn_kernel, cudaFuncAttributeMaxDynamicSharedMemorySize, SMEM_BYTES);

    prep_kernel<<<1024, 256>>>(W_k, U, b, dv_loc, dv_rho, eps_w0, eps_w);
    rnn_kernel<<<BATCH/ROWS_CTA, 256, SMEM_BYTES>>>(inputs, eps_s, out);
}

// round 5
// speedup vs baseline: 1.7010x; 1.2234x over previous
#include <cuda_runtime.h>
#include <math.h>

#define NF 101
#define UNITS 125
#define G3 375
#define OUT 202
#define KSZ (UNITS*OUT)
#define NW (KSZ+OUT)
#define TT 70
#define STEPS1 56
#define GAMMA 28
#define BATCH 4096
#define CCONST 0.54132485f

// padded layouts
#define GU 128          // padded units
#define WROW 384        // 3 gates * 128
#define OPAD 256        // padded dense output row

#define OFF_WP 0
#define SZ_WP (NF*WROW)
#define OFF_UP (OFF_WP+SZ_WP)
#define SZ_UP (UNITS*WROW)
#define OFF_B0 (OFF_UP+SZ_UP)
#define OFF_B1 (OFF_B0+WROW)
#define OFF_KP (OFF_B1+WROW)
#define SZ_KP (GAMMA*UNITS*OPAD)
#define OFF_BIAS (OFF_KP+SZ_KP)
#define SZ_BIAS (GAMMA*OPAD)
#define SCRATCH_TOTAL (OFF_BIAS+SZ_BIAS)

__device__ __align__(16) float g_scratch[SCRATCH_TOTAL];

typedef unsigned long long u64;

// ---- packed f32x2 helpers (sm_103a) ----
__device__ __forceinline__ void fma2(u64& d, u64 a, u64 b){
    asm("fma.rn.f32x2 %0, %1, %2, %0;" : "+l"(d) : "l"(a), "l"(b));
}
__device__ __forceinline__ u64 pack2(float x, float y){
    u64 r; asm("mov.b64 %0, {%1,%2};" : "=l"(r) : "f"(x), "f"(y)); return r;
}
__device__ __forceinline__ float2 unpack2(u64 v){
    float2 r; asm("mov.b64 {%0,%1}, %2;" : "=f"(r.x), "=f"(r.y) : "l"(v)); return r;
}

// ---- math ----
__device__ __forceinline__ float sp(float x){          // softplus, stable
    float r = log1pf(__expf(x));
    return (x > 15.f) ? x : r;
}
__device__ __forceinline__ float sigm(float x){
    return __fdividef(1.f, 1.f + __expf(-x));
}
__device__ __forceinline__ float mytanh(float x){
    return __fdividef(2.f, 1.f + __expf(-2.f*x)) - 1.f;
}

// ---- weight prep helpers ----
__device__ __forceinline__ float dvw(int s, int w,
    const float* dv_loc, const float* dv_rho, const float* eps_w0, const float* eps_w)
{
    float sd = 1e-5f + 0.01f * sp(CCONST + dv_rho[w]);
    float e  = (s == 0) ? eps_w0[w] : eps_w[(size_t)(s-1)*NW + w];
    return dv_loc[w] + sd * e;
}

__global__ void prep_kernel(const float* __restrict__ W_k, const float* __restrict__ U,
                            const float* __restrict__ b,   const float* __restrict__ dv_loc,
                            const float* __restrict__ dv_rho, const float* __restrict__ eps_w0,
                            const float* __restrict__ eps_w)
{
    for (int i = blockIdx.x*blockDim.x + threadIdx.x; i < SCRATCH_TOTAL; i += gridDim.x*blockDim.x){
        float v = 0.f;
        if (i < OFF_UP){
            int idx = i - OFF_WP; int k = idx / WROW, c = idx % WROW;
            int g = c / GU, u = c % GU;
            v = (u < UNITS) ? W_k[k*G3 + g*UNITS + u] : 0.f;
        } else if (i < OFF_B0){
            int idx = i - OFF_UP; int k = idx / WROW, c = idx % WROW;
            int g = c / GU, u = c % GU;
            v = (u < UNITS) ? U[k*G3 + g*UNITS + u] : 0.f;
        } else if (i < OFF_B1){
            int c = i - OFF_B0; int g = c / GU, u = c % GU;
            v = (u < UNITS) ? b[g*UNITS + u] : 0.f;
        } else if (i < OFF_KP){
            int c = i - OFF_B1; int g = c / GU, u = c % GU;
            v = (u < UNITS) ? b[G3 + g*UNITS + u] : 0.f;
        } else if (i < OFF_BIAS){
            int idx = i - OFF_KP; int s = idx / (UNITS*OPAD);
            int rem = idx % (UNITS*OPAD); int u = rem / OPAD, o = rem % OPAD;
            if (o < OUT) v = dvw(s, u*OUT + o, dv_loc, dv_rho, eps_w0, eps_w);
        } else {
            int idx = i - OFF_BIAS; int s = idx / OPAD, o = idx % OPAD;
            if (o < OUT) v = dvw(s, KSZ + o, dv_loc, dv_rho, eps_w0, eps_w);
        }
        g_scratch[i] = v;
    }
}

// ---- main persistent RNN kernel: column-split across warps ----
#define ROWS_CTA 16
#define HS 129            // u64 stride per row of h  (padded vs 128 to dodge bank conflicts)
#define XS 105            // u64 stride per row of x
#define YS 208            // float stride per row of y

#define SMEM_BYTES (ROWS_CTA*HS*8 + ROWS_CTA*XS*8 + ROWS_CTA*YS*4)

// GRU step: warp w owns unit-pairs [w*8, w*8+8) of all 3 gates.
// lane: p = w*8 + (lane&7), rows r0 = 4*(lane>>3) .. +4
__device__ __forceinline__ void gru_step(u64* __restrict__ sh_h, const u64* __restrict__ sh_x,
                                         int warp, int lane)
{
    const int p  = warp*8 + (lane & 7);      // u64 column (unit pair) 0..63
    const int r0 = (lane >> 3) * 4;          // 0,4,8,12
    u64 amx[3][4], ami[3][4];
    const u64* b0 = (const u64*)(g_scratch + OFF_B0);
    const u64* b1 = (const u64*)(g_scratch + OFF_B1);
    #pragma unroll
    for (int g = 0; g < 3; ++g){
        u64 v0 = b0[g*64 + p], v1 = b1[g*64 + p];
        #pragma unroll
        for (int r = 0; r < 4; ++r){ amx[g][r] = v0; ami[g][r] = v1; }
    }

    // mx = x @ W_k (+b0)
    const u64* W = (const u64*)(g_scratch + OFF_WP) + p;
    #pragma unroll 4
    for (int k = 0; k < NF; ++k){
        u64 xv[4];
        #pragma unroll
        for (int r = 0; r < 4; ++r) xv[r] = sh_x[(r0+r)*XS + k];
        const u64* wk = W + k*192;
        #pragma unroll
        for (int g = 0; g < 3; ++g){
            u64 w = wk[g*64];
            #pragma unroll
            for (int r = 0; r < 4; ++r) fma2(amx[g][r], w, xv[r]);
        }
    }
    // mi = h @ U (+b1)
    const u64* Uq = (const u64*)(g_scratch + OFF_UP) + p;
    #pragma unroll 4
    for (int k = 0; k < UNITS; ++k){
        u64 hv[4];
        #pragma unroll
        for (int r = 0; r < 4; ++r) hv[r] = sh_h[(r0+r)*HS + k];
        const u64* wk = Uq + k*192;
        #pragma unroll
        for (int g = 0; g < 3; ++g){
            u64 w = wk[g*64];
            #pragma unroll
            for (int r = 0; r < 4; ++r) fma2(ami[g][r], w, hv[r]);
        }
    }
    __syncthreads();   // everyone done reading old h
    #pragma unroll
    for (int r = 0; r < 4; ++r){
        float2 xz = unpack2(amx[0][r]), rz = unpack2(ami[0][r]);
        float2 xr = unpack2(amx[1][r]), rr = unpack2(ami[1][r]);
        float2 xh = unpack2(amx[2][r]), rh = unpack2(ami[2][r]);
        float hold0 = unpack2(sh_h[(r0+r)*HS + 2*p]).x;
        float hold1 = unpack2(sh_h[(r0+r)*HS + 2*p + 1]).x;
        float z0 = sigm(xz.x + rz.x), z1 = sigm(xz.y + rz.y);
        float g0 = sigm(xr.x + rr.x), g1 = sigm(xr.y + rr.y);
        float c0 = mytanh(xh.x + g0*rh.x), c1 = mytanh(xh.y + g1*rh.y);
        float h0 = z0*hold0 + (1.f - z0)*c0;
        float h1 = z1*hold1 + (1.f - z1)*c1;
        sh_h[(r0+r)*HS + 2*p]     = pack2(h0, h0);
        sh_h[(r0+r)*HS + 2*p + 1] = pack2(h1, h1);
    }
    __syncthreads();   // h_new visible before anyone reads it
}

// Dense variational step: warp w owns output u64-pairs [w*16, w*16+16)
// lane: p = w*16 + (lane&15), rows r0 = 8*(lane>>4) .. +8
__device__ __forceinline__ void dense_step(int s, const u64* __restrict__ sh_h,
                                           float* __restrict__ sh_y, int warp, int lane)
{
    const int p  = warp*16 + (lane & 15);    // u64 column 0..127
    const int r0 = (lane >> 4) * 8;          // 0 or 8
    u64 acc[8];
    {
        u64 bv = ((const u64*)(g_scratch + OFF_BIAS))[s*128 + p];
        #pragma unroll
        for (int r = 0; r < 8; ++r) acc[r] = bv;
    }
    const u64* Kp = (const u64*)(g_scratch + OFF_KP) + (size_t)s*(UNITS*128) + p;
    #pragma unroll 4
    for (int u = 0; u < UNITS; ++u){
        u64 w = Kp[u*128];
        u64 hv[8];
        #pragma unroll
        for (int r = 0; r < 8; ++r) hv[r] = sh_h[(r0+r)*HS + u];
        #pragma unroll
        for (int r = 0; r < 8; ++r) fma2(acc[r], w, hv[r]);
    }
    const int o = 2*p;
    if (o + 1 < YS){
        #pragma unroll
        for (int r = 0; r < 8; ++r){
            float2 v = unpack2(acc[r]);
            sh_y[(r0+r)*YS + o]     = v.x;
            sh_y[(r0+r)*YS + o + 1] = v.y;
        }
    }
    __syncthreads();
}

__global__ void __launch_bounds__(256, 2)
rnn_kernel(const float* __restrict__ inputs, const float* __restrict__ eps_s,
           float* __restrict__ out)
{
    extern __shared__ unsigned char smem[];
    u64*   sh_h = (u64*)smem;                                   // 16*129 u64
    u64*   sh_x = (u64*)(smem + ROWS_CTA*HS*8);                 // 16*105 u64
    float* sh_y = (float*)(smem + ROWS_CTA*HS*8 + ROWS_CTA*XS*8); // 16*208 f32

    const int tid  = threadIdx.x;
    const int lane = tid & 31;
    const int warp = tid >> 5;
    const int row0 = blockIdx.x * ROWS_CTA;

    // h = 0
    for (int i = tid; i < ROWS_CTA*HS; i += 256) sh_h[i] = 0ULL;

    // phase 1: teacher-forced GRU over 56 steps
    for (int t = 0; t < STEPS1; ++t){
        for (int i = tid; i < ROWS_CTA*NF; i += 256){
            int r = i / NF, k = i - r*NF;
            float v = inputs[((size_t)(row0 + r)*TT + t)*NF + k];
            sh_x[r*XS + k] = pack2(v, v);
        }
        __syncthreads();
        gru_step(sh_h, sh_x, warp, lane);
    }

    // y0 + feedback loop
    for (int s = 0; s < GAMMA; ++s){
        if (s > 0){
            for (int i = tid; i < ROWS_CTA*NF; i += 256){
                int r = i / NF, k = i - r*NF;
                float loc = sh_y[r*YS + k];
                float sc  = 1e-5f + 0.05f*sp(CCONST + sh_y[r*YS + NF + k]);
                float xv  = loc + sc * eps_s[((size_t)(s-1)*BATCH + row0 + r)*NF + k];
                sh_x[r*XS + k] = pack2(xv, xv);
            }
            __syncthreads();
            gru_step(sh_h, sh_x, warp, lane);
        }
        dense_step(s, sh_h, sh_y, warp, lane);
        // emit outputs: loc passthrough, scale transform
        for (int i = tid; i < ROWS_CTA*OUT; i += 256){
            int r = i / OUT, o = i - r*OUT;
            float v = sh_y[r*YS + o];
            if (o >= NF) v = 1e-5f + 0.05f*sp(CCONST + v);
            out[((size_t)(row0 + r)*GAMMA + s)*OUT + o] = v;
        }
        // no barrier needed here: sh_y is next written only after the
        // syncthreads inside gru_step/dense_step of the next iteration
    }
}

extern "C" void kernel_launch(void* const* d_in, const int* in_sizes, int n_in,
                              void* d_out, int out_size)
{
    const float* inputs = (const float*)d_in[0];
    const float* W_k    = (const float*)d_in[1];
    const float* U      = (const float*)d_in[2];
    const float* b      = (const float*)d_in[3];
    const float* dv_loc = (const float*)d_in[4];
    const float* dv_rho = (const float*)d_in[5];
    const float* eps_w0 = (const float*)d_in[6];
    const float* eps_w  = (const float*)d_in[7];
    const float* eps_s  = (const float*)d_in[8];
    float* out = (float*)d_out;

    (void)in_sizes; (void)n_in; (void)out_size;

    cudaFuncSetAttribute(rnn_kernel, cudaFuncAttributeMaxDynamicSharedMemorySize, SMEM_BYTES);

    prep_kernel<<<1024, 256>>>(W_k, U, b, dv_loc, dv_rho, eps_w0, eps_w);
    rnn_kernel<<<BATCH/ROWS_CTA, 256, SMEM_BYTES>>>(inputs, eps_s, out);
}